// round 7
// baseline (speedup 1.0000x reference)
#include <cuda_runtime.h>
#include <cstdint>

// Problem dims
#define NB 16
#define NS_SEQ 2048
#define ND 512
#define NH 256
#define NROWS 32768   // NB*NS_SEQ
#define NHID 1024

// ---------------- scratch (static device memory; no allocations) ----------------
__device__ float g_xn[(long)NROWS * ND];
__device__ float g_zx[(long)NROWS * 2048];
__device__ float g_h1[(long)NROWS * ND];
__device__ float g_h2[(long)NROWS * ND];
__device__ float g_gpre[(long)NROWS * NHID];
__device__ unsigned char g_apply[NROWS];

__device__ __forceinline__ float sigf(float x) { return 1.0f / (1.0f + expf(-x)); }

// ---------------- LayerNorm ----------------
template <int COLS, bool RELU>
__global__ __launch_bounds__(128) void ln_kernel(const float* __restrict__ in,
                                                 float* __restrict__ out,
                                                 const float* __restrict__ gamma,
                                                 const float* __restrict__ beta) {
    constexpr int V = COLS / 512;
    long row = blockIdx.x;
    const float4* ip = (const float4*)(in + row * (long)COLS);
    int tid = threadIdx.x;
    float4 v[V];
    float s = 0.f, ss = 0.f;
#pragma unroll
    for (int i = 0; i < V; i++) {
        v[i] = ip[i * 128 + tid];
        s += v[i].x + v[i].y + v[i].z + v[i].w;
        ss += v[i].x * v[i].x + v[i].y * v[i].y + v[i].z * v[i].z + v[i].w * v[i].w;
    }
#pragma unroll
    for (int o = 16; o > 0; o >>= 1) {
        s += __shfl_xor_sync(0xffffffffu, s, o);
        ss += __shfl_xor_sync(0xffffffffu, ss, o);
    }
    __shared__ float red[8];
    int wid = tid >> 5;
    if ((tid & 31) == 0) { red[wid] = s; red[4 + wid] = ss; }
    __syncthreads();
    s = red[0] + red[1] + red[2] + red[3];
    ss = red[4] + red[5] + red[6] + red[7];
    float mean = s * (1.0f / COLS);
    float var = ss * (1.0f / COLS) - mean * mean;
    float rstd = rsqrtf(var + 1e-5f);
    float4* op = (float4*)(out + row * (long)COLS);
#pragma unroll
    for (int i = 0; i < V; i++) {
        int c0 = (i * 128 + tid) * 4;
        float4 g4 = *(const float4*)(gamma + c0);
        float4 b4 = *(const float4*)(beta + c0);
        float4 r;
        r.x = (v[i].x - mean) * rstd * g4.x + b4.x;
        r.y = (v[i].y - mean) * rstd * g4.y + b4.y;
        r.z = (v[i].z - mean) * rstd * g4.z + b4.z;
        r.w = (v[i].w - mean) * rstd * g4.w + b4.w;
        if (RELU) {
            r.x = fmaxf(r.x, 0.f); r.y = fmaxf(r.y, 0.f);
            r.z = fmaxf(r.z, 0.f); r.w = fmaxf(r.w, 0.f);
        }
        op[i * 128 + tid] = r;
    }
}

// ---------------- decide scan ----------------
__global__ void decide_kernel(const float* __restrict__ rnd,
                              const void* __restrict__ maskv,
                              unsigned char* __restrict__ apply) {
    int b = threadIdx.x;
    if (b >= NB) return;
    unsigned int w0 = ((const unsigned int*)maskv)[0];
    int enc = (w0 == 0x01010101u) ? 0 : (w0 == 0x3F800000u) ? 2 : (w0 == 1u) ? 1 : 0;
    const unsigned char* m8 = (const unsigned char*)maskv;
    const int* m32 = (const int*)maskv;
    const float* mf = (const float*)maskv;
    long base = (long)b * NS_SEQ;
    int last = -1000000000;
    int cons = 0;
    for (int pos = 0; pos < NS_SEQ; pos++) {
        float r = rnd[base + pos];
        long i = base + pos;
        bool m = (enc == 0) ? (m8[i] != 0) : (enc == 1) ? (m32[i] != 0) : (mf[i] != 0.0f);
        bool iok = (pos == 0) || (pos - last >= 2);
        bool ap = m && (r < 0.5f) && iok && (cons < 2);
        last = ap ? pos : last;
        cons = ap ? cons + 1 : (m ? 0 : cons);
        apply[i] = ap ? (unsigned char)1 : (unsigned char)0;
    }
}

// ================= tf32 mma.sync GEMM (unchanged, passing) =================
#define SROW 36

__device__ __forceinline__ uint32_t cvt_tf32(float x) {
    uint32_t r; asm("cvt.rn.tf32.f32 %0, %1;" : "=r"(r) : "f"(x)); return r;
}
__device__ __forceinline__ void mma8(float* c, const uint32_t* a, const uint32_t* b) {
    asm volatile("mma.sync.aligned.m16n8k8.row.col.f32.tf32.tf32.f32 "
                 "{%0,%1,%2,%3}, {%4,%5,%6,%7}, {%8,%9}, {%0,%1,%2,%3};"
                 : "+f"(c[0]), "+f"(c[1]), "+f"(c[2]), "+f"(c[3])
                 : "r"(a[0]), "r"(a[1]), "r"(a[2]), "r"(a[3]), "r"(b[0]), "r"(b[1]));
}

template <int MODE>
__global__ __launch_bounds__(256) void tf32_gemm_kernel(
    const float* __restrict__ A1, const float* __restrict__ A2, int Ksplit, int K,
    const float* __restrict__ W, const float* __restrict__ bias,
    float* __restrict__ C, int N,
    const unsigned char* __restrict__ apply, const float* __restrict__ xn) {
    __shared__ uint32_t As[128 * SROW];
    __shared__ uint32_t Bs[128 * SROW];

    const int tid = threadIdx.x;
    const int wid = tid >> 5;
    const int lane = tid & 31;
    const int m0 = blockIdx.y * 128, n0 = blockIdx.x * 128;
    const int lda2 = K - Ksplit;
    const int warp_m = wid & 1, warp_n = wid >> 1;
    const int g4 = lane >> 2;
    const int t4 = lane & 3;

    const int lrow = tid >> 1;
    const int lhalf = tid & 1;

    float acc[4][4][4];
#pragma unroll
    for (int i = 0; i < 4; i++)
#pragma unroll
        for (int j = 0; j < 4; j++)
#pragma unroll
            for (int u = 0; u < 4; u++) acc[i][j][u] = 0.f;

    const int NT = K >> 5;
    float4 av[4], bv[4];
    {
        const int gc = lhalf << 4;
        const float* asrc = (gc < Ksplit) ? (A1 + (long)(m0 + lrow) * Ksplit + gc)
                                          : (A2 + (long)(m0 + lrow) * lda2 + (gc - Ksplit));
        const float* bsrc = W + (long)(n0 + lrow) * K + gc;
#pragma unroll
        for (int q = 0; q < 4; q++) { av[q] = ((const float4*)asrc)[q]; bv[q] = ((const float4*)bsrc)[q]; }
    }
#pragma unroll
    for (int q = 0; q < 4; q++) {
        int cbase = lhalf * 16 + q * 4;
        As[lrow * SROW + cbase + 0] = cvt_tf32(av[q].x);
        As[lrow * SROW + cbase + 1] = cvt_tf32(av[q].y);
        As[lrow * SROW + cbase + 2] = cvt_tf32(av[q].z);
        As[lrow * SROW + cbase + 3] = cvt_tf32(av[q].w);
        Bs[lrow * SROW + cbase + 0] = cvt_tf32(bv[q].x);
        Bs[lrow * SROW + cbase + 1] = cvt_tf32(bv[q].y);
        Bs[lrow * SROW + cbase + 2] = cvt_tf32(bv[q].z);
        Bs[lrow * SROW + cbase + 3] = cvt_tf32(bv[q].w);
    }
    __syncthreads();

    for (int t = 0; t < NT; t++) {
        if (t + 1 < NT) {
            const int gc = ((t + 1) << 5) + (lhalf << 4);
            const float* asrc = (gc < Ksplit) ? (A1 + (long)(m0 + lrow) * Ksplit + gc)
                                              : (A2 + (long)(m0 + lrow) * lda2 + (gc - Ksplit));
            const float* bsrc = W + (long)(n0 + lrow) * K + gc;
#pragma unroll
            for (int q = 0; q < 4; q++) { av[q] = ((const float4*)asrc)[q]; bv[q] = ((const float4*)bsrc)[q]; }
        }
#pragma unroll
        for (int ks = 0; ks < 4; ks++) {
            uint32_t afr[4][4], bfr[4][2];
            const int kc = ks * 8 + t4;
#pragma unroll
            for (int i = 0; i < 4; i++) {
                int r0 = warp_m * 64 + i * 16 + g4;
                afr[i][0] = As[r0 * SROW + kc];
                afr[i][1] = As[(r0 + 8) * SROW + kc];
                afr[i][2] = As[r0 * SROW + kc + 4];
                afr[i][3] = As[(r0 + 8) * SROW + kc + 4];
            }
#pragma unroll
            for (int j = 0; j < 4; j++) {
                int nr = warp_n * 32 + j * 8 + g4;
                bfr[j][0] = Bs[nr * SROW + kc];
                bfr[j][1] = Bs[nr * SROW + kc + 4];
            }
#pragma unroll
            for (int i = 0; i < 4; i++)
#pragma unroll
                for (int j = 0; j < 4; j++) mma8(acc[i][j], afr[i], bfr[j]);
        }
        __syncthreads();
        if (t + 1 < NT) {
#pragma unroll
            for (int q = 0; q < 4; q++) {
                int cbase = lhalf * 16 + q * 4;
                As[lrow * SROW + cbase + 0] = cvt_tf32(av[q].x);
                As[lrow * SROW + cbase + 1] = cvt_tf32(av[q].y);
                As[lrow * SROW + cbase + 2] = cvt_tf32(av[q].z);
                As[lrow * SROW + cbase + 3] = cvt_tf32(av[q].w);
                Bs[lrow * SROW + cbase + 0] = cvt_tf32(bv[q].x);
                Bs[lrow * SROW + cbase + 1] = cvt_tf32(bv[q].y);
                Bs[lrow * SROW + cbase + 2] = cvt_tf32(bv[q].z);
                Bs[lrow * SROW + cbase + 3] = cvt_tf32(bv[q].w);
            }
            __syncthreads();
        }
    }

#pragma unroll
    for (int i = 0; i < 4; i++) {
        long r0 = m0 + warp_m * 64 + i * 16 + g4;
        long r1 = r0 + 8;
        unsigned char ap0 = 0, ap1 = 0;
        if (MODE == 1) { ap0 = apply[r0]; ap1 = apply[r1]; }
#pragma unroll
        for (int j = 0; j < 4; j++) {
            int c = n0 + warp_n * 32 + j * 8 + 2 * t4;
            float v00 = acc[i][j][0] + bias[c];
            float v01 = acc[i][j][1] + bias[c + 1];
            float v10 = acc[i][j][2] + bias[c];
            float v11 = acc[i][j][3] + bias[c + 1];
            if (MODE == 0) {
                *(float2*)(C + r0 * (long)N + c) = make_float2(v00, v01);
                *(float2*)(C + r1 * (long)N + c) = make_float2(v10, v11);
            } else {
                float2 x0 = *(const float2*)(xn + r0 * 512 + c);
                float2 x1 = *(const float2*)(xn + r1 * 512 + c);
                float p00, p01, p10, p11;
                if (c < 256)      { p00 = fminf(fmaxf(v00, 0.f), 1.f); p10 = fminf(fmaxf(v10, 0.f), 1.f); }
                else if (c < 384) { p00 = v00 * 0.3f; p10 = v10 * 0.3f; }
                else if (c < 448) { p00 = v00 * 0.7f; p10 = v10 * 0.7f; }
                else              { p00 = v00 + 0.05f; p10 = v10 + 0.05f; }
                int c1 = c + 1;
                if (c1 < 256)      { p01 = fminf(fmaxf(v01, 0.f), 1.f); p11 = fminf(fmaxf(v11, 0.f), 1.f); }
                else if (c1 < 384) { p01 = v01 * 0.3f; p11 = v11 * 0.3f; }
                else if (c1 < 448) { p01 = v01 * 0.7f; p11 = v11 * 0.7f; }
                else               { p01 = v01 + 0.05f; p11 = v11 + 0.05f; }
                *(float2*)(C + r0 * 512 + c) = make_float2(ap0 ? p00 : x0.x, ap0 ? p01 : x0.y);
                *(float2*)(C + r1 * 512 + c) = make_float2(ap1 ? p10 : x1.x, ap1 ? p11 : x1.y);
            }
        }
    }
}

// ================= BiLSTM recurrence v3 =================
// 16 clusters x 8 CTAs, 256 thr/CTA. Thread (u=tid>>3, kg=tid&7) owns all 4 gate
// rows of unit ug=rank*32+u over k-slice [kg*32,kg*32+32); weights packed (i,f)/(g,o)
// as f32x2. h exchanged via DSMEM 4-slot ring. Per-CTA mbarrier count=256: EVERY
// storing thread release-arrives on the mbarrier of the CTA it stored to (correct
// PTX-memory-model handoff). Trailing cluster barrier prevents the exit race.

#define LSLICE 528               // 32 k * 16B + 16B pad
#define LBUF (8 * LSLICE)        // 4224 bytes per ring slot
#define NRING 4

__device__ __forceinline__ unsigned long long pk2(float lo, float hi) {
    unsigned long long r; asm("mov.b64 %0, {%1,%2};" : "=l"(r) : "f"(lo), "f"(hi)); return r;
}
__device__ __forceinline__ void upk2(unsigned long long v, float& lo, float& hi) {
    asm("mov.b64 {%0,%1}, %2;" : "=f"(lo), "=f"(hi) : "l"(v));
}
__device__ __forceinline__ void fma2(unsigned long long& d, unsigned long long a, unsigned long long b) {
    asm("fma.rn.f32x2 %0, %1, %2, %0;" : "+l"(d) : "l"(a), "l"(b));
}
__device__ __forceinline__ unsigned long long addx2(unsigned long long a, unsigned long long b) {
    unsigned long long r; asm("add.rn.f32x2 %0, %1, %2;" : "=l"(r) : "l"(a), "l"(b)); return r;
}
__device__ __forceinline__ float ftanh_(float x) {
    float r; asm("tanh.approx.f32 %0, %1;" : "=f"(r) : "f"(x)); return r;
}
__device__ __forceinline__ float fsig(float x) {
    return 0.5f * ftanh_(0.5f * x) + 0.5f;
}
__device__ __forceinline__ void lstm_wait(uint32_t addr, uint32_t parity) {
    asm volatile(
        "{\n\t.reg .pred P;\n\t"
        "WL_%=:\n\t"
        "mbarrier.try_wait.parity.acquire.cluster.shared::cta.b64 P, [%0], %1, 0x989680;\n\t"
        "@P bra.uni WD_%=;\n\t"
        "bra.uni WL_%=;\n\t"
        "WD_%=:\n\t}"
        :: "r"(addr), "r"(parity) : "memory");
}

__global__ __launch_bounds__(256, 1) __cluster_dims__(8, 1, 1)
void lstm_kernel(const float* __restrict__ zx, const float* __restrict__ whh,
                 float* __restrict__ hout) {
    __shared__ __align__(16) char hraw[NRING * LBUF];
    __shared__ __align__(8) unsigned long long mbar_s;

    const int rank = blockIdx.x & 7;
    const int cl = blockIdx.x >> 3;
    const int dir = cl >> 3;
    const int bp = cl & 7;
    const int tid = threadIdx.x;
    const int kg = tid & 7;
    const int u = tid >> 3;
    const int ug = rank * 32 + u;
    const int K0 = kg * 32;
    const int gate = kg >> 1;
    const int bsel = kg & 1;

    unsigned long long wIF[32], wGO[32];
    {
        const float* wi = whh + ((long)dir * 1024 + 0 * 256 + ug) * 256 + K0;
        const float* wf = whh + ((long)dir * 1024 + 1 * 256 + ug) * 256 + K0;
        const float* wg = whh + ((long)dir * 1024 + 2 * 256 + ug) * 256 + K0;
        const float* wo = whh + ((long)dir * 1024 + 3 * 256 + ug) * 256 + K0;
#pragma unroll
        for (int k = 0; k < 32; k++) { wIF[k] = pk2(wi[k], wf[k]); wGO[k] = pk2(wg[k], wo[k]); }
    }

    const uint32_t hbase = (uint32_t)__cvta_generic_to_shared(hraw);
    const uint32_t mbaddr = (uint32_t)__cvta_generic_to_shared(&mbar_s);

    for (int i = tid; i < NRING * LBUF / 4; i += 256) ((uint32_t*)hraw)[i] = 0;
    if (tid == 0)
        asm volatile("mbarrier.init.shared.b64 [%0], 256;" :: "r"(mbaddr) : "memory");
    __syncthreads();
    asm volatile("barrier.cluster.arrive.aligned;" ::: "memory");
    asm volatile("barrier.cluster.wait.aligned;" ::: "memory");

    // this thread's store/arrive target: CTA 'kg'
    uint32_t rHbase, rMbar;
    asm("mapa.shared::cluster.u32 %0, %1, %2;" : "=r"(rHbase) : "r"(hbase), "r"(kg));
    asm("mapa.shared::cluster.u32 %0, %1, %2;" : "=r"(rMbar) : "r"(mbaddr), "r"(kg));
    const uint32_t stoff = ug * 16 + rank * 16;  // slice(rank)*LSLICE + (ug&31)*16

    float c0 = 0.f, c1 = 0.f;
    const long nb0 = (long)(bp * 2) * NS_SEQ;
    const long nb1 = nb0 + NS_SEQ;
    const long zrow = bsel ? nb1 : nb0;
    const int zcol = dir * 1024 + gate * 256 + ug;
    const int oidx = dir * 256 + ug;

    for (int t = 0; t < NS_SEQ; t++) {
        const int s = dir ? (NS_SEQ - 1 - t) : t;
        float zxv = zx[(zrow + s) * 2048 + zcol];   // issued before the wait

        if (t > 0) lstm_wait(mbaddr, (t - 1) & 1);

        const int rb = t & 3, wb = (t + 1) & 3;
        const char* rp = hraw + rb * LBUF + kg * LSLICE;
        unsigned long long aIF0 = 0, aIF1 = 0, aGO0 = 0, aGO1 = 0;
#pragma unroll
        for (int k = 0; k < 32; k++) {
            ulonglong2 hv = *(const ulonglong2*)(rp + k * 16);
            fma2(aIF0, wIF[k], hv.x);
            fma2(aIF1, wIF[k], hv.y);
            fma2(aGO0, wGO[k], hv.x);
            fma2(aGO1, wGO[k], hv.y);
        }
        {
            unsigned long long zIF = (gate == 0) ? pk2(zxv, 0.f) : (gate == 1) ? pk2(0.f, zxv) : 0ull;
            unsigned long long zGO = (gate == 2) ? pk2(zxv, 0.f) : (gate == 3) ? pk2(0.f, zxv) : 0ull;
            aIF0 = addx2(aIF0, bsel ? 0ull : zIF);
            aIF1 = addx2(aIF1, bsel ? zIF : 0ull);
            aGO0 = addx2(aGO0, bsel ? 0ull : zGO);
            aGO1 = addx2(aGO1, bsel ? zGO : 0ull);
        }
#pragma unroll
        for (int o = 1; o < 8; o <<= 1) {
            aIF0 = addx2(aIF0, __shfl_xor_sync(0xffffffffu, aIF0, o));
            aIF1 = addx2(aIF1, __shfl_xor_sync(0xffffffffu, aIF1, o));
            aGO0 = addx2(aGO0, __shfl_xor_sync(0xffffffffu, aGO0, o));
            aGO1 = addx2(aGO1, __shfl_xor_sync(0xffffffffu, aGO1, o));
        }
        float zi0, zf0, zg0, zo0, zi1, zf1, zg1, zo1;
        upk2(aIF0, zi0, zf0); upk2(aGO0, zg0, zo0);
        upk2(aIF1, zi1, zf1); upk2(aGO1, zg1, zo1);

        c0 = fsig(zf0) * c0 + fsig(zi0) * ftanh_(zg0);
        float h0 = fsig(zo0) * ftanh_(c0);
        c1 = fsig(zf1) * c1 + fsig(zi1) * ftanh_(zg1);
        float h1 = fsig(zo1) * ftanh_(c1);

        // duplicated h {h0,h0} {h1,h1} into dest CTA kg, ring slot wb
        {
            uint32_t dst = rHbase + wb * LBUF + stoff;
            unsigned long long p0 = pk2(h0, h0), p1 = pk2(h1, h1);
            asm volatile("st.shared::cluster.b64 [%0], %1;" :: "r"(dst), "l"(p0) : "memory");
            asm volatile("st.shared::cluster.b64 [%0], %1;" :: "r"(dst + 8), "l"(p1) : "memory");
        }
        if (kg == 0) {
            hout[(nb0 + s) * 512 + oidx] = h0;
            hout[(nb1 + s) * 512 + oidx] = h1;
        }
        // release-arrive by the storing thread itself (orders its own stores)
        asm volatile("mbarrier.arrive.release.cluster.shared::cluster.b64 _, [%0];"
                     :: "r"(rMbar) : "memory");
    }

    // exit-race protection: keep SMEM alive until all peers' stores/arrives land
    asm volatile("barrier.cluster.arrive.aligned;" ::: "memory");
    asm volatile("barrier.cluster.wait.aligned;" ::: "memory");
}

// ---------------- launch ----------------
extern "C" void kernel_launch(void* const* d_in, const int* in_sizes, int n_in,
                              void* d_out, int out_size) {
    const float* features = (const float*)d_in[0];
    const void* mask = d_in[1];
    const float* rnd = (const float*)d_in[2];
    const float* ln_g = (const float*)d_in[3];
    const float* ln_b = (const float*)d_in[4];
    const float* Wih0 = (const float*)d_in[5];
    const float* Whh0 = (const float*)d_in[6];
    const float* b0 = (const float*)d_in[7];
    const float* Wih1 = (const float*)d_in[8];
    const float* Whh1 = (const float*)d_in[9];
    const float* b1 = (const float*)d_in[10];
    const float* gW1 = (const float*)d_in[11];
    const float* gb1 = (const float*)d_in[12];
    const float* gln_g = (const float*)d_in[13];
    const float* gln_b = (const float*)d_in[14];
    const float* gW2 = (const float*)d_in[15];
    const float* gb2 = (const float*)d_in[16];
    float* out = (float*)d_out;

    float *xn, *zx, *h1, *h2, *gpre;
    unsigned char* apl;
    cudaGetSymbolAddress((void**)&xn, g_xn);
    cudaGetSymbolAddress((void**)&zx, g_zx);
    cudaGetSymbolAddress((void**)&h1, g_h1);
    cudaGetSymbolAddress((void**)&h2, g_h2);
    cudaGetSymbolAddress((void**)&gpre, g_gpre);
    cudaGetSymbolAddress((void**)&apl, g_apply);

    // 1. LayerNorm(features) -> xn
    ln_kernel<512, false><<<NROWS, 128>>>(features, xn, ln_g, ln_b);
    // 2. decide scan -> apply
    decide_kernel<<<1, 32>>>(rnd, mask, apl);
    // 3. layer0 input projections: zx = xn @ Wih0cat^T + b0   [32768 x 2048]
    tf32_gemm_kernel<0><<<dim3(16, 256), 256>>>(xn, xn, 512, 512, Wih0, b0, zx, 2048, nullptr, nullptr);
    // 4. layer0 recurrence -> h1
    lstm_kernel<<<128, 256>>>(zx, Whh0, h1);
    // 5. layer1 input projections: zx = h1 @ Wih1cat^T + b1
    tf32_gemm_kernel<0><<<dim3(16, 256), 256>>>(h1, h1, 512, 512, Wih1, b1, zx, 2048, nullptr, nullptr);
    // 6. layer1 recurrence -> h2
    lstm_kernel<<<128, 256>>>(zx, Whh1, h2);
    // 7. gpre = [xn | h2] @ gW1^T + gb1   [32768 x 1024]
    tf32_gemm_kernel<0><<<dim3(8, 256), 256>>>(xn, h2, 512, 1024, gW1, gb1, gpre, 1024, nullptr, nullptr);
    // 8. LN + ReLU in place
    ln_kernel<1024, true><<<NROWS, 128>>>(gpre, gpre, gln_g, gln_b);
    // 9. orn (first 512 cols of gW2) + ornament transform + apply-select -> out
    tf32_gemm_kernel<1><<<dim3(4, 256), 256>>>(gpre, gpre, 1024, 1024, gW2, gb2, out, 512, apl, xn);
}

// round 8
// speedup vs baseline: 1.0205x; 1.0205x over previous
#include <cuda_runtime.h>
#include <cstdint>

// Problem dims
#define NB 16
#define NS_SEQ 2048
#define ND 512
#define NH 256
#define NROWS 32768   // NB*NS_SEQ
#define NHID 1024

// ---------------- scratch (static device memory; no allocations) ----------------
__device__ float g_xn[(long)NROWS * ND];
__device__ float g_zx[(long)NROWS * 2048];
__device__ float g_h1[(long)NROWS * ND];
__device__ float g_h2[(long)NROWS * ND];
__device__ float g_gpre[(long)NROWS * NHID];
__device__ unsigned char g_apply[NROWS];

__device__ __forceinline__ float sigf(float x) { return 1.0f / (1.0f + expf(-x)); }

// ---------------- LayerNorm ----------------
template <int COLS, bool RELU>
__global__ __launch_bounds__(128) void ln_kernel(const float* __restrict__ in,
                                                 float* __restrict__ out,
                                                 const float* __restrict__ gamma,
                                                 const float* __restrict__ beta) {
    constexpr int V = COLS / 512;
    long row = blockIdx.x;
    const float4* ip = (const float4*)(in + row * (long)COLS);
    int tid = threadIdx.x;
    float4 v[V];
    float s = 0.f, ss = 0.f;
#pragma unroll
    for (int i = 0; i < V; i++) {
        v[i] = ip[i * 128 + tid];
        s += v[i].x + v[i].y + v[i].z + v[i].w;
        ss += v[i].x * v[i].x + v[i].y * v[i].y + v[i].z * v[i].z + v[i].w * v[i].w;
    }
#pragma unroll
    for (int o = 16; o > 0; o >>= 1) {
        s += __shfl_xor_sync(0xffffffffu, s, o);
        ss += __shfl_xor_sync(0xffffffffu, ss, o);
    }
    __shared__ float red[8];
    int wid = tid >> 5;
    if ((tid & 31) == 0) { red[wid] = s; red[4 + wid] = ss; }
    __syncthreads();
    s = red[0] + red[1] + red[2] + red[3];
    ss = red[4] + red[5] + red[6] + red[7];
    float mean = s * (1.0f / COLS);
    float var = ss * (1.0f / COLS) - mean * mean;
    float rstd = rsqrtf(var + 1e-5f);
    float4* op = (float4*)(out + row * (long)COLS);
#pragma unroll
    for (int i = 0; i < V; i++) {
        int c0 = (i * 128 + tid) * 4;
        float4 g4 = *(const float4*)(gamma + c0);
        float4 b4 = *(const float4*)(beta + c0);
        float4 r;
        r.x = (v[i].x - mean) * rstd * g4.x + b4.x;
        r.y = (v[i].y - mean) * rstd * g4.y + b4.y;
        r.z = (v[i].z - mean) * rstd * g4.z + b4.z;
        r.w = (v[i].w - mean) * rstd * g4.w + b4.w;
        if (RELU) {
            r.x = fmaxf(r.x, 0.f); r.y = fmaxf(r.y, 0.f);
            r.z = fmaxf(r.z, 0.f); r.w = fmaxf(r.w, 0.f);
        }
        op[i * 128 + tid] = r;
    }
}

// ---------------- decide scan ----------------
__global__ void decide_kernel(const float* __restrict__ rnd,
                              const void* __restrict__ maskv,
                              unsigned char* __restrict__ apply) {
    int b = threadIdx.x;
    if (b >= NB) return;
    unsigned int w0 = ((const unsigned int*)maskv)[0];
    int enc = (w0 == 0x01010101u) ? 0 : (w0 == 0x3F800000u) ? 2 : (w0 == 1u) ? 1 : 0;
    const unsigned char* m8 = (const unsigned char*)maskv;
    const int* m32 = (const int*)maskv;
    const float* mf = (const float*)maskv;
    long base = (long)b * NS_SEQ;
    int last = -1000000000;
    int cons = 0;
    for (int pos = 0; pos < NS_SEQ; pos++) {
        float r = rnd[base + pos];
        long i = base + pos;
        bool m = (enc == 0) ? (m8[i] != 0) : (enc == 1) ? (m32[i] != 0) : (mf[i] != 0.0f);
        bool iok = (pos == 0) || (pos - last >= 2);
        bool ap = m && (r < 0.5f) && iok && (cons < 2);
        last = ap ? pos : last;
        cons = ap ? cons + 1 : (m ? 0 : cons);
        apply[i] = ap ? (unsigned char)1 : (unsigned char)0;
    }
}

// ================= tf32 mma.sync GEMM (unchanged, passing) =================
#define SROW 36

__device__ __forceinline__ uint32_t cvt_tf32(float x) {
    uint32_t r; asm("cvt.rn.tf32.f32 %0, %1;" : "=r"(r) : "f"(x)); return r;
}
__device__ __forceinline__ void mma8(float* c, const uint32_t* a, const uint32_t* b) {
    asm volatile("mma.sync.aligned.m16n8k8.row.col.f32.tf32.tf32.f32 "
                 "{%0,%1,%2,%3}, {%4,%5,%6,%7}, {%8,%9}, {%0,%1,%2,%3};"
                 : "+f"(c[0]), "+f"(c[1]), "+f"(c[2]), "+f"(c[3])
                 : "r"(a[0]), "r"(a[1]), "r"(a[2]), "r"(a[3]), "r"(b[0]), "r"(b[1]));
}

template <int MODE>
__global__ __launch_bounds__(256) void tf32_gemm_kernel(
    const float* __restrict__ A1, const float* __restrict__ A2, int Ksplit, int K,
    const float* __restrict__ W, const float* __restrict__ bias,
    float* __restrict__ C, int N,
    const unsigned char* __restrict__ apply, const float* __restrict__ xn) {
    __shared__ uint32_t As[128 * SROW];
    __shared__ uint32_t Bs[128 * SROW];

    const int tid = threadIdx.x;
    const int wid = tid >> 5;
    const int lane = tid & 31;
    const int m0 = blockIdx.y * 128, n0 = blockIdx.x * 128;
    const int lda2 = K - Ksplit;
    const int warp_m = wid & 1, warp_n = wid >> 1;
    const int g4 = lane >> 2;
    const int t4 = lane & 3;

    const int lrow = tid >> 1;
    const int lhalf = tid & 1;

    float acc[4][4][4];
#pragma unroll
    for (int i = 0; i < 4; i++)
#pragma unroll
        for (int j = 0; j < 4; j++)
#pragma unroll
            for (int u = 0; u < 4; u++) acc[i][j][u] = 0.f;

    const int NT = K >> 5;
    float4 av[4], bv[4];
    {
        const int gc = lhalf << 4;
        const float* asrc = (gc < Ksplit) ? (A1 + (long)(m0 + lrow) * Ksplit + gc)
                                          : (A2 + (long)(m0 + lrow) * lda2 + (gc - Ksplit));
        const float* bsrc = W + (long)(n0 + lrow) * K + gc;
#pragma unroll
        for (int q = 0; q < 4; q++) { av[q] = ((const float4*)asrc)[q]; bv[q] = ((const float4*)bsrc)[q]; }
    }
#pragma unroll
    for (int q = 0; q < 4; q++) {
        int cbase = lhalf * 16 + q * 4;
        As[lrow * SROW + cbase + 0] = cvt_tf32(av[q].x);
        As[lrow * SROW + cbase + 1] = cvt_tf32(av[q].y);
        As[lrow * SROW + cbase + 2] = cvt_tf32(av[q].z);
        As[lrow * SROW + cbase + 3] = cvt_tf32(av[q].w);
        Bs[lrow * SROW + cbase + 0] = cvt_tf32(bv[q].x);
        Bs[lrow * SROW + cbase + 1] = cvt_tf32(bv[q].y);
        Bs[lrow * SROW + cbase + 2] = cvt_tf32(bv[q].z);
        Bs[lrow * SROW + cbase + 3] = cvt_tf32(bv[q].w);
    }
    __syncthreads();

    for (int t = 0; t < NT; t++) {
        if (t + 1 < NT) {
            const int gc = ((t + 1) << 5) + (lhalf << 4);
            const float* asrc = (gc < Ksplit) ? (A1 + (long)(m0 + lrow) * Ksplit + gc)
                                              : (A2 + (long)(m0 + lrow) * lda2 + (gc - Ksplit));
            const float* bsrc = W + (long)(n0 + lrow) * K + gc;
#pragma unroll
            for (int q = 0; q < 4; q++) { av[q] = ((const float4*)asrc)[q]; bv[q] = ((const float4*)bsrc)[q]; }
        }
#pragma unroll
        for (int ks = 0; ks < 4; ks++) {
            uint32_t afr[4][4], bfr[4][2];
            const int kc = ks * 8 + t4;
#pragma unroll
            for (int i = 0; i < 4; i++) {
                int r0 = warp_m * 64 + i * 16 + g4;
                afr[i][0] = As[r0 * SROW + kc];
                afr[i][1] = As[(r0 + 8) * SROW + kc];
                afr[i][2] = As[r0 * SROW + kc + 4];
                afr[i][3] = As[(r0 + 8) * SROW + kc + 4];
            }
#pragma unroll
            for (int j = 0; j < 4; j++) {
                int nr = warp_n * 32 + j * 8 + g4;
                bfr[j][0] = Bs[nr * SROW + kc];
                bfr[j][1] = Bs[nr * SROW + kc + 4];
            }
#pragma unroll
            for (int i = 0; i < 4; i++)
#pragma unroll
                for (int j = 0; j < 4; j++) mma8(acc[i][j], afr[i], bfr[j]);
        }
        __syncthreads();
        if (t + 1 < NT) {
#pragma unroll
            for (int q = 0; q < 4; q++) {
                int cbase = lhalf * 16 + q * 4;
                As[lrow * SROW + cbase + 0] = cvt_tf32(av[q].x);
                As[lrow * SROW + cbase + 1] = cvt_tf32(av[q].y);
                As[lrow * SROW + cbase + 2] = cvt_tf32(av[q].z);
                As[lrow * SROW + cbase + 3] = cvt_tf32(av[q].w);
                Bs[lrow * SROW + cbase + 0] = cvt_tf32(bv[q].x);
                Bs[lrow * SROW + cbase + 1] = cvt_tf32(bv[q].y);
                Bs[lrow * SROW + cbase + 2] = cvt_tf32(bv[q].z);
                Bs[lrow * SROW + cbase + 3] = cvt_tf32(bv[q].w);
            }
            __syncthreads();
        }
    }

#pragma unroll
    for (int i = 0; i < 4; i++) {
        long r0 = m0 + warp_m * 64 + i * 16 + g4;
        long r1 = r0 + 8;
        unsigned char ap0 = 0, ap1 = 0;
        if (MODE == 1) { ap0 = apply[r0]; ap1 = apply[r1]; }
#pragma unroll
        for (int j = 0; j < 4; j++) {
            int c = n0 + warp_n * 32 + j * 8 + 2 * t4;
            float v00 = acc[i][j][0] + bias[c];
            float v01 = acc[i][j][1] + bias[c + 1];
            float v10 = acc[i][j][2] + bias[c];
            float v11 = acc[i][j][3] + bias[c + 1];
            if (MODE == 0) {
                *(float2*)(C + r0 * (long)N + c) = make_float2(v00, v01);
                *(float2*)(C + r1 * (long)N + c) = make_float2(v10, v11);
            } else {
                float2 x0 = *(const float2*)(xn + r0 * 512 + c);
                float2 x1 = *(const float2*)(xn + r1 * 512 + c);
                float p00, p01, p10, p11;
                if (c < 256)      { p00 = fminf(fmaxf(v00, 0.f), 1.f); p10 = fminf(fmaxf(v10, 0.f), 1.f); }
                else if (c < 384) { p00 = v00 * 0.3f; p10 = v10 * 0.3f; }
                else if (c < 448) { p00 = v00 * 0.7f; p10 = v10 * 0.7f; }
                else              { p00 = v00 + 0.05f; p10 = v10 + 0.05f; }
                int c1 = c + 1;
                if (c1 < 256)      { p01 = fminf(fmaxf(v01, 0.f), 1.f); p11 = fminf(fmaxf(v11, 0.f), 1.f); }
                else if (c1 < 384) { p01 = v01 * 0.3f; p11 = v11 * 0.3f; }
                else if (c1 < 448) { p01 = v01 * 0.7f; p11 = v11 * 0.7f; }
                else               { p01 = v01 + 0.05f; p11 = v11 + 0.05f; }
                *(float2*)(C + r0 * 512 + c) = make_float2(ap0 ? p00 : x0.x, ap0 ? p01 : x0.y);
                *(float2*)(C + r1 * 512 + c) = make_float2(ap1 ? p10 : x1.x, ap1 ? p11 : x1.y);
            }
        }
    }
}

// ================= BiLSTM recurrence v4 =================
// v3 compute (f32x2 FMA, in-thread butterfly gates, MUFU tanh) + v1 sync
// (one barrier.cluster per step; its arrive/wait is release/acquire at cluster
// scope, ordering the per-thread st.shared::cluster h-stores). No mbarriers.

#define LSLICE 528               // 32 k * 16B + 16B pad
#define LBUF (8 * LSLICE)        // 4224 bytes per ring slot
#define NRING 2

__device__ __forceinline__ unsigned long long pk2(float lo, float hi) {
    unsigned long long r; asm("mov.b64 %0, {%1,%2};" : "=l"(r) : "f"(lo), "f"(hi)); return r;
}
__device__ __forceinline__ void upk2(unsigned long long v, float& lo, float& hi) {
    asm("mov.b64 {%0,%1}, %2;" : "=f"(lo), "=f"(hi) : "l"(v));
}
__device__ __forceinline__ void fma2(unsigned long long& d, unsigned long long a, unsigned long long b) {
    asm("fma.rn.f32x2 %0, %1, %2, %0;" : "+l"(d) : "l"(a), "l"(b));
}
__device__ __forceinline__ unsigned long long addx2(unsigned long long a, unsigned long long b) {
    unsigned long long r; asm("add.rn.f32x2 %0, %1, %2;" : "=l"(r) : "l"(a), "l"(b)); return r;
}
__device__ __forceinline__ float ftanh_(float x) {
    float r; asm("tanh.approx.f32 %0, %1;" : "=f"(r) : "f"(x)); return r;
}
__device__ __forceinline__ float fsig(float x) {
    return 0.5f * ftanh_(0.5f * x) + 0.5f;
}

__global__ __launch_bounds__(256, 1) __cluster_dims__(8, 1, 1)
void lstm_kernel(const float* __restrict__ zx, const float* __restrict__ whh,
                 float* __restrict__ hout) {
    __shared__ __align__(16) char hraw[NRING * LBUF];

    const int rank = blockIdx.x & 7;
    const int cl = blockIdx.x >> 3;
    const int dir = cl >> 3;
    const int bp = cl & 7;
    const int tid = threadIdx.x;
    const int kg = tid & 7;
    const int u = tid >> 3;
    const int ug = rank * 32 + u;
    const int K0 = kg * 32;
    const int gate = kg >> 1;
    const int bsel = kg & 1;

    unsigned long long wIF[32], wGO[32];
    {
        const float* wi = whh + ((long)dir * 1024 + 0 * 256 + ug) * 256 + K0;
        const float* wf = whh + ((long)dir * 1024 + 1 * 256 + ug) * 256 + K0;
        const float* wg = whh + ((long)dir * 1024 + 2 * 256 + ug) * 256 + K0;
        const float* wo = whh + ((long)dir * 1024 + 3 * 256 + ug) * 256 + K0;
#pragma unroll
        for (int k = 0; k < 32; k++) { wIF[k] = pk2(wi[k], wf[k]); wGO[k] = pk2(wg[k], wo[k]); }
    }

    const uint32_t hbase = (uint32_t)__cvta_generic_to_shared(hraw);

    for (int i = tid; i < NRING * LBUF / 4; i += 256) ((uint32_t*)hraw)[i] = 0;
    __syncthreads();
    asm volatile("barrier.cluster.arrive.aligned;" ::: "memory");
    asm volatile("barrier.cluster.wait.aligned;" ::: "memory");

    // this thread's store target: CTA 'kg', slice 'rank', entry u
    uint32_t rHbase;
    asm("mapa.shared::cluster.u32 %0, %1, %2;" : "=r"(rHbase) : "r"(hbase), "r"(kg));
    const uint32_t stoff = rank * LSLICE + u * 16;

    float c0 = 0.f, c1 = 0.f;
    const long nb0 = (long)(bp * 2) * NS_SEQ;
    const long nb1 = nb0 + NS_SEQ;
    const long zrow = bsel ? nb1 : nb0;
    const int zcol = dir * 1024 + gate * 256 + ug;
    const int oidx = dir * 256 + ug;

    for (int t = 0; t < NS_SEQ; t++) {
        const int s = dir ? (NS_SEQ - 1 - t) : t;
        float zxv = zx[(zrow + s) * 2048 + zcol];

        const int rb = t & 1, wb = rb ^ 1;
        const char* rp = hraw + rb * LBUF + kg * LSLICE;
        unsigned long long aIF0 = 0, aIF1 = 0, aGO0 = 0, aGO1 = 0;
#pragma unroll
        for (int k = 0; k < 32; k++) {
            ulonglong2 hv = *(const ulonglong2*)(rp + k * 16);
            fma2(aIF0, wIF[k], hv.x);
            fma2(aIF1, wIF[k], hv.y);
            fma2(aGO0, wGO[k], hv.x);
            fma2(aGO1, wGO[k], hv.y);
        }
        {
            unsigned long long zIF = (gate == 0) ? pk2(zxv, 0.f) : (gate == 1) ? pk2(0.f, zxv) : 0ull;
            unsigned long long zGO = (gate == 2) ? pk2(zxv, 0.f) : (gate == 3) ? pk2(0.f, zxv) : 0ull;
            aIF0 = addx2(aIF0, bsel ? 0ull : zIF);
            aIF1 = addx2(aIF1, bsel ? zIF : 0ull);
            aGO0 = addx2(aGO0, bsel ? 0ull : zGO);
            aGO1 = addx2(aGO1, bsel ? zGO : 0ull);
        }
#pragma unroll
        for (int o = 1; o < 8; o <<= 1) {
            aIF0 = addx2(aIF0, __shfl_xor_sync(0xffffffffu, aIF0, o));
            aIF1 = addx2(aIF1, __shfl_xor_sync(0xffffffffu, aIF1, o));
            aGO0 = addx2(aGO0, __shfl_xor_sync(0xffffffffu, aGO0, o));
            aGO1 = addx2(aGO1, __shfl_xor_sync(0xffffffffu, aGO1, o));
        }
        float zi0, zf0, zg0, zo0, zi1, zf1, zg1, zo1;
        upk2(aIF0, zi0, zf0); upk2(aGO0, zg0, zo0);
        upk2(aIF1, zi1, zf1); upk2(aGO1, zg1, zo1);

        c0 = fsig(zf0) * c0 + fsig(zi0) * ftanh_(zg0);
        float h0 = fsig(zo0) * ftanh_(c0);
        c1 = fsig(zf1) * c1 + fsig(zi1) * ftanh_(zg1);
        float h1 = fsig(zo1) * ftanh_(c1);

        // duplicated h {h0,h0} {h1,h1} into dest CTA kg, ring slot wb
        {
            uint32_t dst = rHbase + wb * LBUF + stoff;
            unsigned long long p0 = pk2(h0, h0), p1 = pk2(h1, h1);
            asm volatile("st.shared::cluster.b64 [%0], %1;" :: "r"(dst), "l"(p0) : "memory");
            asm volatile("st.shared::cluster.b64 [%0], %1;" :: "r"(dst + 8), "l"(p1) : "memory");
        }
        if (kg == 0) {
            hout[(nb0 + s) * 512 + oidx] = h0;
            hout[(nb1 + s) * 512 + oidx] = h1;
        }
        // one cluster barrier per step: releases our stores, acquires peers'
        asm volatile("barrier.cluster.arrive.aligned;" ::: "memory");
        asm volatile("barrier.cluster.wait.aligned;" ::: "memory");
    }
}

// ---------------- launch ----------------
extern "C" void kernel_launch(void* const* d_in, const int* in_sizes, int n_in,
                              void* d_out, int out_size) {
    const float* features = (const float*)d_in[0];
    const void* mask = d_in[1];
    const float* rnd = (const float*)d_in[2];
    const float* ln_g = (const float*)d_in[3];
    const float* ln_b = (const float*)d_in[4];
    const float* Wih0 = (const float*)d_in[5];
    const float* Whh0 = (const float*)d_in[6];
    const float* b0 = (const float*)d_in[7];
    const float* Wih1 = (const float*)d_in[8];
    const float* Whh1 = (const float*)d_in[9];
    const float* b1 = (const float*)d_in[10];
    const float* gW1 = (const float*)d_in[11];
    const float* gb1 = (const float*)d_in[12];
    const float* gln_g = (const float*)d_in[13];
    const float* gln_b = (const float*)d_in[14];
    const float* gW2 = (const float*)d_in[15];
    const float* gb2 = (const float*)d_in[16];
    float* out = (float*)d_out;

    float *xn, *zx, *h1, *h2, *gpre;
    unsigned char* apl;
    cudaGetSymbolAddress((void**)&xn, g_xn);
    cudaGetSymbolAddress((void**)&zx, g_zx);
    cudaGetSymbolAddress((void**)&h1, g_h1);
    cudaGetSymbolAddress((void**)&h2, g_h2);
    cudaGetSymbolAddress((void**)&gpre, g_gpre);
    cudaGetSymbolAddress((void**)&apl, g_apply);

    // 1. LayerNorm(features) -> xn
    ln_kernel<512, false><<<NROWS, 128>>>(features, xn, ln_g, ln_b);
    // 2. decide scan -> apply
    decide_kernel<<<1, 32>>>(rnd, mask, apl);
    // 3. layer0 input projections: zx = xn @ Wih0cat^T + b0   [32768 x 2048]
    tf32_gemm_kernel<0><<<dim3(16, 256), 256>>>(xn, xn, 512, 512, Wih0, b0, zx, 2048, nullptr, nullptr);
    // 4. layer0 recurrence -> h1
    lstm_kernel<<<128, 256>>>(zx, Whh0, h1);
    // 5. layer1 input projections: zx = h1 @ Wih1cat^T + b1
    tf32_gemm_kernel<0><<<dim3(16, 256), 256>>>(h1, h1, 512, 512, Wih1, b1, zx, 2048, nullptr, nullptr);
    // 6. layer1 recurrence -> h2
    lstm_kernel<<<128, 256>>>(zx, Whh1, h2);
    // 7. gpre = [xn | h2] @ gW1^T + gb1   [32768 x 1024]
    tf32_gemm_kernel<0><<<dim3(8, 256), 256>>>(xn, h2, 512, 1024, gW1, gb1, gpre, 1024, nullptr, nullptr);
    // 8. LN + ReLU in place
    ln_kernel<1024, true><<<NROWS, 128>>>(gpre, gpre, gln_g, gln_b);
    // 9. orn (first 512 cols of gW2) + ornament transform + apply-select -> out
    tf32_gemm_kernel<1><<<dim3(4, 256), 256>>>(gpre, gpre, 1024, 1024, gW2, gb2, out, 512, apl, xn);
}

// round 9
// speedup vs baseline: 1.3687x; 1.3412x over previous
#include <cuda_runtime.h>
#include <cstdint>

// Problem dims
#define NB 16
#define NS_SEQ 2048
#define ND 512
#define NH 256
#define NROWS 32768   // NB*NS_SEQ
#define NHID 1024

// ---------------- scratch (static device memory; no allocations) ----------------
__device__ float g_xn[(long)NROWS * ND];
__device__ float g_zx[(long)NROWS * 2048];
__device__ float g_h1[(long)NROWS * ND];
__device__ float g_h2[(long)NROWS * ND];
__device__ float g_gpre[(long)NROWS * NHID];
__device__ unsigned char g_apply[NROWS];

// ---------------- helpers ----------------
__device__ __forceinline__ float ftanh_(float x) {
    float r; asm("tanh.approx.f32 %0, %1;" : "=f"(r) : "f"(x)); return r;
}
__device__ __forceinline__ float fsig(float x) {
    return 0.5f * ftanh_(0.5f * x) + 0.5f;
}

// ---------------- LayerNorm ----------------
template <int COLS, bool RELU>
__global__ __launch_bounds__(128) void ln_kernel(const float* __restrict__ in,
                                                 float* __restrict__ out,
                                                 const float* __restrict__ gamma,
                                                 const float* __restrict__ beta) {
    constexpr int V = COLS / 512;
    long row = blockIdx.x;
    const float4* ip = (const float4*)(in + row * (long)COLS);
    int tid = threadIdx.x;
    float4 v[V];
    float s = 0.f, ss = 0.f;
#pragma unroll
    for (int i = 0; i < V; i++) {
        v[i] = ip[i * 128 + tid];
        s += v[i].x + v[i].y + v[i].z + v[i].w;
        ss += v[i].x * v[i].x + v[i].y * v[i].y + v[i].z * v[i].z + v[i].w * v[i].w;
    }
#pragma unroll
    for (int o = 16; o > 0; o >>= 1) {
        s += __shfl_xor_sync(0xffffffffu, s, o);
        ss += __shfl_xor_sync(0xffffffffu, ss, o);
    }
    __shared__ float red[8];
    int wid = tid >> 5;
    if ((tid & 31) == 0) { red[wid] = s; red[4 + wid] = ss; }
    __syncthreads();
    s = red[0] + red[1] + red[2] + red[3];
    ss = red[4] + red[5] + red[6] + red[7];
    float mean = s * (1.0f / COLS);
    float var = ss * (1.0f / COLS) - mean * mean;
    float rstd = rsqrtf(var + 1e-5f);
    float4* op = (float4*)(out + row * (long)COLS);
#pragma unroll
    for (int i = 0; i < V; i++) {
        int c0 = (i * 128 + tid) * 4;
        float4 g4 = *(const float4*)(gamma + c0);
        float4 b4 = *(const float4*)(beta + c0);
        float4 r;
        r.x = (v[i].x - mean) * rstd * g4.x + b4.x;
        r.y = (v[i].y - mean) * rstd * g4.y + b4.y;
        r.z = (v[i].z - mean) * rstd * g4.z + b4.z;
        r.w = (v[i].w - mean) * rstd * g4.w + b4.w;
        if (RELU) {
            r.x = fmaxf(r.x, 0.f); r.y = fmaxf(r.y, 0.f);
            r.z = fmaxf(r.z, 0.f); r.w = fmaxf(r.w, 0.f);
        }
        op[i * 128 + tid] = r;
    }
}

// ---------------- decide scan ----------------
__global__ void decide_kernel(const float* __restrict__ rnd,
                              const void* __restrict__ maskv,
                              unsigned char* __restrict__ apply) {
    int b = threadIdx.x;
    if (b >= NB) return;
    unsigned int w0 = ((const unsigned int*)maskv)[0];
    int enc = (w0 == 0x01010101u) ? 0 : (w0 == 0x3F800000u) ? 2 : (w0 == 1u) ? 1 : 0;
    const unsigned char* m8 = (const unsigned char*)maskv;
    const int* m32 = (const int*)maskv;
    const float* mf = (const float*)maskv;
    long base = (long)b * NS_SEQ;
    int last = -1000000000;
    int cons = 0;
    for (int pos = 0; pos < NS_SEQ; pos++) {
        float r = rnd[base + pos];
        long i = base + pos;
        bool m = (enc == 0) ? (m8[i] != 0) : (enc == 1) ? (m32[i] != 0) : (mf[i] != 0.0f);
        bool iok = (pos == 0) || (pos - last >= 2);
        bool ap = m && (r < 0.5f) && iok && (cons < 2);
        last = ap ? pos : last;
        cons = ap ? cons + 1 : (m ? 0 : cons);
        apply[i] = ap ? (unsigned char)1 : (unsigned char)0;
    }
}

// ================= tf32 mma.sync GEMM with ldmatrix fragments =================
// C[M,N] = A[M,K] @ W[N,K]^T + bias ; CTA tile 128x128, K-chunk 32.
// 8 warps 2x4 (warp tile 64x32). Fragments loaded via ldmatrix.m8n8.x4.b16;
// with SROW=36 (144B row stride) the 8 rows of each 8x8 matrix hit disjoint
// 4-bank groups -> conflict-free 128B phases.
#define SROW 36

__device__ __forceinline__ uint32_t cvt_tf32(float x) {
    uint32_t r; asm("cvt.rn.tf32.f32 %0, %1;" : "=r"(r) : "f"(x)); return r;
}
__device__ __forceinline__ void mma8(float* c, const uint32_t* a, const uint32_t* b) {
    asm volatile("mma.sync.aligned.m16n8k8.row.col.f32.tf32.tf32.f32 "
                 "{%0,%1,%2,%3}, {%4,%5,%6,%7}, {%8,%9}, {%0,%1,%2,%3};"
                 : "+f"(c[0]), "+f"(c[1]), "+f"(c[2]), "+f"(c[3])
                 : "r"(a[0]), "r"(a[1]), "r"(a[2]), "r"(a[3]), "r"(b[0]), "r"(b[1]));
}
__device__ __forceinline__ void ldsm4(uint32_t* r, uint32_t addr) {
    asm volatile("ldmatrix.sync.aligned.m8n8.x4.shared.b16 {%0,%1,%2,%3}, [%4];"
                 : "=r"(r[0]), "=r"(r[1]), "=r"(r[2]), "=r"(r[3]) : "r"(addr));
}

template <int MODE>
__global__ __launch_bounds__(256) void tf32_gemm_kernel(
    const float* __restrict__ A1, const float* __restrict__ A2, int Ksplit, int K,
    const float* __restrict__ W, const float* __restrict__ bias,
    float* __restrict__ C, int N,
    const unsigned char* __restrict__ apply, const float* __restrict__ xn) {
    __shared__ uint32_t As[128 * SROW];
    __shared__ uint32_t Bs[128 * SROW];

    const int tid = threadIdx.x;
    const int wid = tid >> 5;
    const int lane = tid & 31;
    const int m0 = blockIdx.y * 128, n0 = blockIdx.x * 128;
    const int lda2 = K - Ksplit;
    const int warp_m = wid & 1, warp_n = wid >> 1;
    const int g4 = lane >> 2;
    const int t4 = lane & 3;

    const int lrow = tid >> 1;
    const int lhalf = tid & 1;

    // ldmatrix per-lane byte offsets (within As/Bs)
    const uint32_t aBase = (uint32_t)__cvta_generic_to_shared(As);
    const uint32_t bBase = (uint32_t)__cvta_generic_to_shared(Bs);
    // A matrices: rows base + (lane&15); kq advance by (lane>>4)
    const uint32_t a_off = aBase + (uint32_t)(warp_m * 64 + (lane & 15)) * 144u
                         + (uint32_t)(lane >> 4) * 16u;
    // B matrices: rows warp_n*32 + (lane&7) + ((lane>>4)<<3); kq advance by ((lane>>3)&1)
    const uint32_t b_off = bBase + (uint32_t)(warp_n * 32 + (lane & 7) + ((lane >> 4) << 3)) * 144u
                         + (uint32_t)((lane >> 3) & 1) * 16u;

    float acc[4][4][4];
#pragma unroll
    for (int i = 0; i < 4; i++)
#pragma unroll
        for (int j = 0; j < 4; j++)
#pragma unroll
            for (int u = 0; u < 4; u++) acc[i][j][u] = 0.f;

    const int NT = K >> 5;
    float4 av[4], bv[4];
    {
        const int gc = lhalf << 4;
        const float* asrc = (gc < Ksplit) ? (A1 + (long)(m0 + lrow) * Ksplit + gc)
                                          : (A2 + (long)(m0 + lrow) * lda2 + (gc - Ksplit));
        const float* bsrc = W + (long)(n0 + lrow) * K + gc;
#pragma unroll
        for (int q = 0; q < 4; q++) { av[q] = ((const float4*)asrc)[q]; bv[q] = ((const float4*)bsrc)[q]; }
    }
#pragma unroll
    for (int q = 0; q < 4; q++) {
        int cbase = lrow * SROW + lhalf * 16 + q * 4;
        *(uint4*)&As[cbase] = make_uint4(cvt_tf32(av[q].x), cvt_tf32(av[q].y), cvt_tf32(av[q].z), cvt_tf32(av[q].w));
        *(uint4*)&Bs[cbase] = make_uint4(cvt_tf32(bv[q].x), cvt_tf32(bv[q].y), cvt_tf32(bv[q].z), cvt_tf32(bv[q].w));
    }
    __syncthreads();

    for (int t = 0; t < NT; t++) {
        if (t + 1 < NT) {
            const int gc = ((t + 1) << 5) + (lhalf << 4);
            const float* asrc = (gc < Ksplit) ? (A1 + (long)(m0 + lrow) * Ksplit + gc)
                                              : (A2 + (long)(m0 + lrow) * lda2 + (gc - Ksplit));
            const float* bsrc = W + (long)(n0 + lrow) * K + gc;
#pragma unroll
            for (int q = 0; q < 4; q++) { av[q] = ((const float4*)asrc)[q]; bv[q] = ((const float4*)bsrc)[q]; }
        }
#pragma unroll
        for (int ks = 0; ks < 4; ks++) {
            uint32_t afr[4][4], bfr[4][2];
            const uint32_t kqb = (uint32_t)(ks * 32);
#pragma unroll
            for (int i = 0; i < 4; i++)
                ldsm4(afr[i], a_off + (uint32_t)(i * 16 * 144) + kqb);
#pragma unroll
            for (int p = 0; p < 2; p++) {
                uint32_t br[4];
                ldsm4(br, b_off + (uint32_t)(p * 16 * 144) + kqb);
                bfr[2 * p][0] = br[0]; bfr[2 * p][1] = br[1];
                bfr[2 * p + 1][0] = br[2]; bfr[2 * p + 1][1] = br[3];
            }
#pragma unroll
            for (int i = 0; i < 4; i++)
#pragma unroll
                for (int j = 0; j < 4; j++) mma8(acc[i][j], afr[i], bfr[j]);
        }
        __syncthreads();
        if (t + 1 < NT) {
#pragma unroll
            for (int q = 0; q < 4; q++) {
                int cbase = lrow * SROW + lhalf * 16 + q * 4;
                *(uint4*)&As[cbase] = make_uint4(cvt_tf32(av[q].x), cvt_tf32(av[q].y), cvt_tf32(av[q].z), cvt_tf32(av[q].w));
                *(uint4*)&Bs[cbase] = make_uint4(cvt_tf32(bv[q].x), cvt_tf32(bv[q].y), cvt_tf32(bv[q].z), cvt_tf32(bv[q].w));
            }
            __syncthreads();
        }
    }

#pragma unroll
    for (int i = 0; i < 4; i++) {
        long r0 = m0 + warp_m * 64 + i * 16 + g4;
        long r1 = r0 + 8;
        unsigned char ap0 = 0, ap1 = 0;
        if (MODE == 1) { ap0 = apply[r0]; ap1 = apply[r1]; }
#pragma unroll
        for (int j = 0; j < 4; j++) {
            int c = n0 + warp_n * 32 + j * 8 + 2 * t4;
            float v00 = acc[i][j][0] + bias[c];
            float v01 = acc[i][j][1] + bias[c + 1];
            float v10 = acc[i][j][2] + bias[c];
            float v11 = acc[i][j][3] + bias[c + 1];
            if (MODE == 0) {
                *(float2*)(C + r0 * (long)N + c) = make_float2(v00, v01);
                *(float2*)(C + r1 * (long)N + c) = make_float2(v10, v11);
            } else {
                float2 x0 = *(const float2*)(xn + r0 * 512 + c);
                float2 x1 = *(const float2*)(xn + r1 * 512 + c);
                float p00, p01, p10, p11;
                if (c < 256)      { p00 = fminf(fmaxf(v00, 0.f), 1.f); p10 = fminf(fmaxf(v10, 0.f), 1.f); }
                else if (c < 384) { p00 = v00 * 0.3f; p10 = v10 * 0.3f; }
                else if (c < 448) { p00 = v00 * 0.7f; p10 = v10 * 0.7f; }
                else              { p00 = v00 + 0.05f; p10 = v10 + 0.05f; }
                int c1 = c + 1;
                if (c1 < 256)      { p01 = fminf(fmaxf(v01, 0.f), 1.f); p11 = fminf(fmaxf(v11, 0.f), 1.f); }
                else if (c1 < 384) { p01 = v01 * 0.3f; p11 = v11 * 0.3f; }
                else if (c1 < 448) { p01 = v01 * 0.7f; p11 = v11 * 0.7f; }
                else               { p01 = v01 + 0.05f; p11 = v11 + 0.05f; }
                *(float2*)(C + r0 * 512 + c) = make_float2(ap0 ? p00 : x0.x, ap0 ? p01 : x0.y);
                *(float2*)(C + r1 * 512 + c) = make_float2(ap1 ? p10 : x1.x, ap1 ? p11 : x1.y);
            }
        }
    }
}

// ================= BiLSTM recurrence (proven v1 structure; MUFU gates) =================
__device__ __forceinline__ void cluster_sync_() {
    asm volatile("barrier.cluster.arrive.aligned;" ::: "memory");
    asm volatile("barrier.cluster.wait.aligned;" ::: "memory");
}

__global__ __launch_bounds__(256, 1) __cluster_dims__(8, 1, 1)
void lstm_kernel(const float* __restrict__ zx, const float* __restrict__ whh,
                 float* __restrict__ hout) {
    __shared__ float hbuf[2][2][272];
    __shared__ float zred[128][2];

    const int rank = blockIdx.x & 7;
    const int cl = blockIdx.x >> 3;
    const int dir = cl >> 3;
    const int bp = cl & 7;
    const int tid = threadIdx.x;
    const int kg = tid & 3;
    const int rg = tid >> 2;

    const int zr0 = ((rg >> 5) << 8) + rank * 32 + (rg & 31);
    const int zr1 = zr0 + 512;

    float4 w0[16], w1[16];
    {
        const float4* p0 = (const float4*)(whh + ((long)dir * 1024 + zr0) * 256 + kg * 64);
        const float4* p1 = (const float4*)(whh + ((long)dir * 1024 + zr1) * 256 + kg * 64);
#pragma unroll
        for (int q = 0; q < 16; q++) { w0[q] = p0[q]; w1[q] = p1[q]; }
    }

    for (int i = tid; i < 2 * 2 * 272; i += 256) (&hbuf[0][0][0])[i] = 0.f;
    __syncthreads();
    cluster_sync_();

    float cst = 0.f;
    const int gu = tid & 31;
    const int gb = tid >> 5;
    const long nb0 = (long)(bp * 2) * NS_SEQ;
    const long nb1 = (long)(bp * 2 + 1) * NS_SEQ;
    const long zc0 = (long)dir * 1024 + zr0;
    const long zc1 = zc0 + 512;

    float zx00 = 0, zx01 = 0, zx10 = 0, zx11 = 0;
    if (kg == 0) {
        int s0 = dir ? (NS_SEQ - 1) : 0;
        zx00 = zx[(nb0 + s0) * 2048 + zc0];
        zx01 = zx[(nb1 + s0) * 2048 + zc0];
        zx10 = zx[(nb0 + s0) * 2048 + zc1];
        zx11 = zx[(nb1 + s0) * 2048 + zc1];
    }

    int buf = 0;
    for (int t = 0; t < NS_SEQ; t++) {
        const int s = dir ? (NS_SEQ - 1 - t) : t;
        float nx00 = 0, nx01 = 0, nx10 = 0, nx11 = 0;
        if (kg == 0 && t < NS_SEQ - 1) {
            int sn = dir ? (NS_SEQ - 2 - t) : (t + 1);
            nx00 = zx[(nb0 + sn) * 2048 + zc0];
            nx01 = zx[(nb1 + sn) * 2048 + zc0];
            nx10 = zx[(nb0 + sn) * 2048 + zc1];
            nx11 = zx[(nb1 + sn) * 2048 + zc1];
        }
        float a00 = 0, a01 = 0, a10 = 0, a11 = 0;
        const float4* h0 = (const float4*)(&hbuf[buf][0][kg * 68]);
        const float4* h1p = (const float4*)(&hbuf[buf][1][kg * 68]);
#pragma unroll
        for (int q = 0; q < 16; q++) {
            float4 hv = h0[q];
            a00 += w0[q].x * hv.x; a00 += w0[q].y * hv.y; a00 += w0[q].z * hv.z; a00 += w0[q].w * hv.w;
            a10 += w1[q].x * hv.x; a10 += w1[q].y * hv.y; a10 += w1[q].z * hv.z; a10 += w1[q].w * hv.w;
        }
#pragma unroll
        for (int q = 0; q < 16; q++) {
            float4 hv = h1p[q];
            a01 += w0[q].x * hv.x; a01 += w0[q].y * hv.y; a01 += w0[q].z * hv.z; a01 += w0[q].w * hv.w;
            a11 += w1[q].x * hv.x; a11 += w1[q].y * hv.y; a11 += w1[q].z * hv.z; a11 += w1[q].w * hv.w;
        }
        a00 += __shfl_xor_sync(0xffffffffu, a00, 1); a00 += __shfl_xor_sync(0xffffffffu, a00, 2);
        a01 += __shfl_xor_sync(0xffffffffu, a01, 1); a01 += __shfl_xor_sync(0xffffffffu, a01, 2);
        a10 += __shfl_xor_sync(0xffffffffu, a10, 1); a10 += __shfl_xor_sync(0xffffffffu, a10, 2);
        a11 += __shfl_xor_sync(0xffffffffu, a11, 1); a11 += __shfl_xor_sync(0xffffffffu, a11, 2);
        if (kg == 0) {
            zred[rg][0] = a00 + zx00;
            zred[rg][1] = a01 + zx01;
            zred[rg + 64][0] = a10 + zx10;
            zred[rg + 64][1] = a11 + zx11;
        }
        __syncthreads();
        if (tid < 64) {
            float zi = zred[gu][gb];
            float zf = zred[32 + gu][gb];
            float zg = zred[64 + gu][gb];
            float zo = zred[96 + gu][gb];
            float ig = fsig(zi), fg = fsig(zf), gg = ftanh_(zg), og = fsig(zo);
            cst = fg * cst + ig * gg;
            float h = og * ftanh_(cst);
            const int guG = rank * 32 + gu;
            const int off = ((guG >> 6) * 68) + (guG & 63);
            float* dst = &hbuf[buf ^ 1][gb][off];
            uint32_t laddr = (uint32_t)__cvta_generic_to_shared(dst);
#pragma unroll
            for (int p = 0; p < 8; p++) {
                uint32_t raddr;
                asm volatile("mapa.shared::cluster.u32 %0, %1, %2;" : "=r"(raddr) : "r"(laddr), "r"(p));
                asm volatile("st.shared::cluster.f32 [%0], %1;" :: "r"(raddr), "f"(h));
            }
            const long nb = gb ? nb1 : nb0;
            hout[(nb + s) * 512 + dir * 256 + guG] = h;
        }
        cluster_sync_();
        buf ^= 1;
        zx00 = nx00; zx01 = nx01; zx10 = nx10; zx11 = nx11;
    }
}

// ---------------- launch ----------------
extern "C" void kernel_launch(void* const* d_in, const int* in_sizes, int n_in,
                              void* d_out, int out_size) {
    const float* features = (const float*)d_in[0];
    const void* mask = d_in[1];
    const float* rnd = (const float*)d_in[2];
    const float* ln_g = (const float*)d_in[3];
    const float* ln_b = (const float*)d_in[4];
    const float* Wih0 = (const float*)d_in[5];
    const float* Whh0 = (const float*)d_in[6];
    const float* b0 = (const float*)d_in[7];
    const float* Wih1 = (const float*)d_in[8];
    const float* Whh1 = (const float*)d_in[9];
    const float* b1 = (const float*)d_in[10];
    const float* gW1 = (const float*)d_in[11];
    const float* gb1 = (const float*)d_in[12];
    const float* gln_g = (const float*)d_in[13];
    const float* gln_b = (const float*)d_in[14];
    const float* gW2 = (const float*)d_in[15];
    const float* gb2 = (const float*)d_in[16];
    float* out = (float*)d_out;

    float *xn, *zx, *h1, *h2, *gpre;
    unsigned char* apl;
    cudaGetSymbolAddress((void**)&xn, g_xn);
    cudaGetSymbolAddress((void**)&zx, g_zx);
    cudaGetSymbolAddress((void**)&h1, g_h1);
    cudaGetSymbolAddress((void**)&h2, g_h2);
    cudaGetSymbolAddress((void**)&gpre, g_gpre);
    cudaGetSymbolAddress((void**)&apl, g_apply);

    // 1. LayerNorm(features) -> xn
    ln_kernel<512, false><<<NROWS, 128>>>(features, xn, ln_g, ln_b);
    // 2. decide scan -> apply
    decide_kernel<<<1, 32>>>(rnd, mask, apl);
    // 3. layer0 input projections: zx = xn @ Wih0cat^T + b0   [32768 x 2048]
    tf32_gemm_kernel<0><<<dim3(16, 256), 256>>>(xn, xn, 512, 512, Wih0, b0, zx, 2048, nullptr, nullptr);
    // 4. layer0 recurrence -> h1
    lstm_kernel<<<128, 256>>>(zx, Whh0, h1);
    // 5. layer1 input projections: zx = h1 @ Wih1cat^T + b1
    tf32_gemm_kernel<0><<<dim3(16, 256), 256>>>(h1, h1, 512, 512, Wih1, b1, zx, 2048, nullptr, nullptr);
    // 6. layer1 recurrence -> h2
    lstm_kernel<<<128, 256>>>(zx, Whh1, h2);
    // 7. gpre = [xn | h2] @ gW1^T + gb1   [32768 x 1024]
    tf32_gemm_kernel<0><<<dim3(8, 256), 256>>>(xn, h2, 512, 1024, gW1, gb1, gpre, 1024, nullptr, nullptr);
    // 8. LN + ReLU in place
    ln_kernel<1024, true><<<NROWS, 128>>>(gpre, gpre, gln_g, gln_b);
    // 9. orn (first 512 cols of gW2) + ornament transform + apply-select -> out
    tf32_gemm_kernel<1><<<dim3(4, 256), 256>>>(gpre, gpre, 1024, 1024, gW2, gb2, out, 512, apl, xn);
}